// round 7
// baseline (speedup 1.0000x reference)
#include <cuda_runtime.h>
#include <cuda_bf16.h>
#include <math.h>

// Problem constants (fixed by setup_inputs)
#define BATCH   16
#define LEN     262144
#define NFFT    1024
#define HOP     256
#define NT      1025          // frames
#define NF      513           // rfft bins (valid)
#define NFQ     528           // padded pitch (16 * 33, 16B-aligned rows)
#define NFP     33            // freq patches
#define NTP     65            // time patches
#define NP      2145          // patches per batch
#define KSEL    643           // int(2145*0.3)
#define MAGP    (BATCH*NT*NFQ)

// Scratch (static device memory; no allocation allowed)
__device__ float g_mag[3ll * MAGP];       // [sig][b][t][f(pitch 528)]
__device__ float g_kgs[BATCH * NP];
__device__ float g_pl [BATCH * NP];
__device__ float g_bsel[BATCH];
__device__ float g_bkgs[BATCH];
__device__ int   g_bpos[BATCH];

// Compile-time 5-bit bit-reverse (folds to immediates under #pragma unroll).
__device__ __host__ __forceinline__ constexpr int brev5(int j) {
    return ((j & 1) << 4) | ((j & 2) << 2) | (j & 4) | ((j & 8) >> 2) | ((j & 16) >> 4);
}

// ---------------------------------------------------------------------------
// Fully-unrolled register FFT-32, DIT, input already in bit-reversed slots,
// natural-order output. All indices and twiddles are compile-time constants.
// ---------------------------------------------------------------------------
__device__ __forceinline__ void fft32_nr(float* xr, float* xi) {
    constexpr float C32[16] = {
        1.0f,          0.980785280f,  0.923879533f,  0.831469612f,
        0.707106781f,  0.555570233f,  0.382683432f,  0.195090322f,
        0.0f,         -0.195090322f, -0.382683432f, -0.555570233f,
       -0.707106781f, -0.831469612f, -0.923879533f, -0.980785280f };
    constexpr float S32[16] = {
        0.0f,          0.195090322f,  0.382683432f,  0.555570233f,
        0.707106781f,  0.831469612f,  0.923879533f,  0.980785280f,
        1.0f,          0.980785280f,  0.923879533f,  0.831469612f,
        0.707106781f,  0.555570233f,  0.382683432f,  0.195090322f };
#pragma unroll
    for (int s = 1; s <= 5; s++) {
        const int h = 1 << (s - 1);
#pragma unroll
        for (int g = 0; g < 32; g += (1 << s)) {
#pragma unroll
            for (int j = 0; j < h; j++) {
                const float wr =  C32[j << (5 - s)];
                const float wi = -S32[j << (5 - s)];
                const int a = g + j, c = g + j + h;
                float tr = wr * xr[c] - wi * xi[c];
                float ti = wr * xi[c] + wi * xr[c];
                xr[c] = xr[a] - tr; xi[c] = xi[a] - ti;
                xr[a] = xr[a] + tr; xi[a] = xi[a] + ti;
            }
        }
    }
}

// ---------------------------------------------------------------------------
// Kernel 1: STFT magnitudes. One warp = one complex-1024 FFT carrying TWO
// frames (two-for-one real trick). Four-step 32x32.
// R7 INVARIANT: xr/xi are NEVER indexed by a value that is not a literal
// constant after unrolling. All runtime-indexed accesses go through shared
// memory (the float2 slab), which tolerates dynamic addressing.
// ---------------------------------------------------------------------------
__global__ __launch_bounds__(128, 5) void stft_kernel(
    const float* __restrict__ xs, const float* __restrict__ xt,
    const float* __restrict__ xg, int block0)
{
    const int lane = threadIdx.x & 31;
    const int w    = threadIdx.x >> 5;
    const int pair = (block0 + blockIdx.x) * 4 + w; // 24624 pairs total (exact)

    int sig = pair / (BATCH * 513);
    int rem = pair - sig * (BATCH * 513);
    int b   = rem / 513;
    int m   = rem - b * 513;

    const float* x = (sig == 0) ? xs : (sig == 1 ? xt : xg);
    x += (size_t)b * LEN;

    __shared__ float2 SZ[4][1056];     // pitch-33 complex, per-warp slab
    float2* sz = SZ[w];

    const int ta    = 2 * m;
    const bool hasb = (m < 512);                  // frame 2m+1 valid?
    const int base  = ta * HOP - 512;             // reflect-pad origin

    float xr[32], xi[32];

    // ---- Load: 40 rows via an 8-deep ring (constant indices when unrolled).
    // Frame B row n2 == frame A row n2+8 (hop 256 = 8 rows of 32).
    float ring[8];
#pragma unroll
    for (int j = 0; j < 8; j++) {
        int sa = base + j * 32 + lane;
        ring[j] = x[min(abs(sa), abs(2 * LEN - 2 - sa))];
    }
#pragma unroll
    for (int n2 = 0; n2 < 32; n2++) {
        int sb = base + (n2 + 8) * 32 + lane;
        float f = x[min(abs(sb), abs(2 * LEN - 2 - sb))];
        xr[brev5(n2)] = ring[n2 & 7];     // all indices literal after unroll
        xi[brev5(n2)] = hasb ? f : 0.f;
        ring[n2 & 7] = f;
    }
    fft32_nr(xr, xi);

    // ---- twiddle by e^{-2pi i n1 k2 / 1024}, 4 independent chains ----
    const int n1 = lane;
    {
        float ssn, cc;
        sincospif(-(float)n1 * (1.0f / 512.0f), &ssn, &cc);
        float w1r = cc,                  w1i = ssn;
        float w2r = w1r*w1r - w1i*w1i,   w2i = 2.f*w1r*w1i;
        float w3r = w2r*w1r - w2i*w1i,   w3i = w2r*w1i + w2i*w1r;
        float w4r = w2r*w2r - w2i*w2i,   w4i = 2.f*w2r*w2i;
#pragma unroll
        for (int r = 0; r < 4; r++) {
            float wr = (r == 0) ? 1.f : (r == 1 ? w1r : (r == 2 ? w2r : w3r));
            float wi = (r == 0) ? 0.f : (r == 1 ? w1i : (r == 2 ? w2i : w3i));
#pragma unroll
            for (int s5 = 0; s5 < 8; s5++) {
                const int k2 = r + 4 * s5;            // literal
                float ar = xr[k2], ai = xi[k2];
                sz[n1 * 33 + k2] = make_float2(ar * wr - ai * wi,
                                               ar * wi + ai * wr);
                float nwr = wr * w4r - wi * w4i;
                float nwi = wr * w4i + wi * w4r;
                wr = nwr; wi = nwi;
            }
        }
    }
    __syncwarp();

    // ---- Pass B: transpose read from shared (constant xr/xi slots) ----
    const int k2c = lane;
#pragma unroll
    for (int nn = 0; nn < 32; nn++) {
        float2 z = sz[nn * 33 + k2c];
        xr[brev5(nn)] = z.x;
        xi[brev5(nn)] = z.y;
    }
    fft32_nr(xr, xi);
    // thread k2c holds Z[k2c + 32*k1] in slot k1 (natural order)

    __syncwarp();   // everyone done reading columns before overwrite

    // ---- Publish Z to shared: Z[k2 + 32*k1] at sz[k1*33 + k2] ----
#pragma unroll
    for (int k1 = 0; k1 < 32; k1++)
        sz[k1 * 33 + k2c] = make_float2(xr[k1], xi[k1]);   // literal slots
    __syncwarp();

    // ---- Unpack two real spectra from shared (runtime LDS idx = fine) ----
    float* outA = g_mag + (size_t)sig * MAGP + ((size_t)b * NT + ta) * NFQ;
    float* outB = outA + NFQ;

#pragma unroll
    for (int it = 0; it < 16; it++) {
        int k  = it * 32 + lane;
        float2 z = sz[it * 33 + lane];
        int kk = (1024 - k) & 1023;
        float2 y = sz[(kk >> 5) * 33 + (kk & 31)];

        float ar = 0.5f * (z.x + y.x), ai = 0.5f * (z.y - y.y);
        float r2a = ar * ar + ai * ai;
        float ma = fmaxf(r2a * rsqrtf(fmaxf(r2a, 1e-24f)), 1e-8f);
        float br_ = 0.5f * (z.y + y.y), bi_ = 0.5f * (y.x - z.x);
        float r2b = br_ * br_ + bi_ * bi_;
        float mb = fmaxf(r2b * rsqrtf(fmaxf(r2b, 1e-24f)), 1e-8f);

        outA[k] = ma;
        if (hasb) outB[k] = mb;
    }
    // tail: k = 512 (lane 0) + zero-fill padding 513..527 (lanes 1..15)
    if (lane == 0) {
        float2 z = sz[16 * 33];
        float maA = fmaxf(fabsf(z.x), 1e-8f);
        float maB = fmaxf(fabsf(z.y), 1e-8f);
        outA[512] = maA;
        if (hasb) outB[512] = maB;
    } else if (lane <= 15) {
        outA[512 + lane] = 0.f;
        if (hasb) outB[512 + lane] = 0.f;
    }
}

// ---------------------------------------------------------------------------
// Kernel 2: per-patch stats. One warp per patch; pure float4 loads on the
// 528-pitch padded layout (rows 16B-aligned). Only t-edge needs a predicate.
// ---------------------------------------------------------------------------
__global__ __launch_bounds__(256) void patch_kernel() {
    const int lane = threadIdx.x & 31;
    const int wid  = threadIdx.x >> 5;
    const int gp   = blockIdx.x * 8 + wid;         // 34320 total (exact)
    const int b  = gp / NP;
    const int p  = gp - b * NP;
    const int fp = p / NTP;
    const int tp = p - fp * NTP;

    const int dt0 = lane >> 2;       // 0..7
    const int q   = lane & 3;        // quad within 16-float row

    float sas = 0.f, sat = 0.f, ssq = 0.f;
#pragma unroll
    for (int j2 = 0; j2 < 2; j2++) {
        int t = tp * 16 + dt0 + j2 * 8;
        if (t < NT) {
            size_t idx = ((size_t)b * NT + t) * NFQ + fp * 16 + q * 4;
            float4 s4 = *(const float4*)(g_mag + idx);
            float4 t4 = *(const float4*)(g_mag + (size_t)MAGP + idx);
            float4 g4 = *(const float4*)(g_mag + 2ll * MAGP + idx);
            sas += fabsf(s4.x - g4.x) + fabsf(s4.y - g4.y)
                 + fabsf(s4.z - g4.z) + fabsf(s4.w - g4.w);
            sat += fabsf(t4.x - g4.x) + fabsf(t4.y - g4.y)
                 + fabsf(t4.z - g4.z) + fabsf(t4.w - g4.w);
            float dx = s4.x - t4.x, dy = s4.y - t4.y;
            float dz = s4.z - t4.z, dw = s4.w - t4.w;
            ssq += dx * dx + dy * dy + dz * dz + dw * dw;
        }
    }
#pragma unroll
    for (int o = 16; o; o >>= 1) {
        sas += __shfl_down_sync(0xffffffffu, sas, o);
        sat += __shfl_down_sync(0xffffffffu, sat, o);
        ssq += __shfl_down_sync(0xffffffffu, ssq, o);
    }
    if (lane == 0) {
        g_kgs[gp] = (sas - sat) * (1.0f / 256.0f);
        g_pl [gp] = ssq * (1.0f / 256.0f);
    }
}

// ---------------------------------------------------------------------------
// Kernel 3: per-batch top-k selection (exact, index-order tie-break) + stats
// ---------------------------------------------------------------------------
__device__ __forceinline__ int bredI(int v, int* scr) {
    const int tid = threadIdx.x;
#pragma unroll
    for (int o = 16; o; o >>= 1) v += __shfl_down_sync(0xffffffffu, v, o);
    __syncthreads();
    if ((tid & 31) == 0) scr[tid >> 5] = v;
    __syncthreads();
    int r = 0;
#pragma unroll
    for (int j = 0; j < 8; j++) r += scr[j];
    return r;
}
__device__ __forceinline__ float bredF(float v, float* scr) {
    const int tid = threadIdx.x;
#pragma unroll
    for (int o = 16; o; o >>= 1) v += __shfl_down_sync(0xffffffffu, v, o);
    __syncthreads();
    if ((tid & 31) == 0) scr[tid >> 5] = v;
    __syncthreads();
    float r = 0.f;
#pragma unroll
    for (int j = 0; j < 8; j++) r += scr[j];
    return r;
}

__global__ __launch_bounds__(256) void select_kernel() {
    const int b = blockIdx.x, tid = threadIdx.x;
    __shared__ unsigned su[NP];
    __shared__ float    spl[NP];
    __shared__ int      eqidx[NP];
    __shared__ int      iscr[8];
    __shared__ float    fscr[8];
    __shared__ int      eqc;

    float ksum = 0.f; int pcnt = 0;
    for (int i = tid; i < NP; i += 256) {
        float kv = g_kgs[b * NP + i];
        spl[i] = g_pl[b * NP + i];
        unsigned bits = __float_as_uint(kv);
        su[i] = (bits & 0x80000000u) ? ~bits : (bits | 0x80000000u); // order-preserving
        ksum += kv;
        pcnt += (kv > 0.f) ? 1 : 0;
    }
    if (tid == 0) eqc = 0;
    __syncthreads();

    ksum = bredF(ksum, fscr);
    pcnt = bredI(pcnt, iscr);

    // binary search for k-th largest key: max v with count(u >= v) >= KSEL
    unsigned long long lo = 0ull, hi = 0xFFFFFFFFull;
    while (lo < hi) {
        unsigned long long mid = lo + ((hi - lo + 1ull) >> 1);
        int c = 0;
        for (int i = tid; i < NP; i += 256)
            c += ((unsigned long long)su[i] >= mid) ? 1 : 0;
        c = bredI(c, iscr);
        if (c >= KSEL) lo = mid; else hi = mid - 1ull;
    }
    const unsigned v = (unsigned)lo;

    int cgt = 0; float ssel = 0.f;
    for (int i = tid; i < NP; i += 256) {
        unsigned u = su[i];
        if (u > v) { cgt++; ssel += spl[i]; }
        else if (u == v) { int pos = atomicAdd(&eqc, 1); eqidx[pos] = i; }
    }
    cgt  = bredI(cgt, iscr);
    ssel = bredF(ssel, fscr);
    __syncthreads();

    if (tid == 0) {
        int need = KSEL - cgt;         // >= 1 by construction
        int ce   = eqc;
        float extra = 0.f;
        if (need >= ce) {
            for (int j = 0; j < ce; j++) extra += spl[eqidx[j]];
        } else {
            int last = -1;
            for (int t2 = 0; t2 < need; t2++) {
                int mn = 0x7fffffff;
                for (int j = 0; j < ce; j++) {
                    int ix = eqidx[j];
                    if (ix > last && ix < mn) mn = ix;
                }
                extra += spl[mn];
                last = mn;
            }
        }
        g_bsel[b] = (ssel + extra) * (1.0f / (float)KSEL);
        g_bkgs[b] = ksum;
        g_bpos[b] = pcnt;
    }
}

// ---------------------------------------------------------------------------
// Kernel 4: finalize the 4 scalars
// ---------------------------------------------------------------------------
__global__ void final_kernel(float* __restrict__ out) {
    const int t = threadIdx.x;
    float s  = (t < BATCH) ? g_bsel[t] : 0.f;
    float kg = (t < BATCH) ? g_bkgs[t] : 0.f;
    float pc = (t < BATCH) ? (float)g_bpos[t] : 0.f;
#pragma unroll
    for (int o = 16; o; o >>= 1) {
        s  += __shfl_down_sync(0xffffffffu, s,  o);
        kg += __shfl_down_sync(0xffffffffu, kg, o);
        pc += __shfl_down_sync(0xffffffffu, pc, o);
    }
    if (t == 0) {
        out[0] = s * (1.0f / (float)BATCH);                      // loss
        out[1] = (float)KSEL / (float)NP;                        // sel_ratio
        out[2] = kg / (float)(BATCH * NP);                       // kgs_mean
        out[3] = pc / (float)(BATCH * NP);                       // kgs_pos_ratio
    }
}

extern "C" void kernel_launch(void* const* d_in, const int* in_sizes, int n_in,
                              void* d_out, int out_size) {
    const float* xs = (const float*)d_in[0];
    const float* xt = (const float*)d_in[1];
    const float* xg = (const float*)d_in[2];
    float* out = (float*)d_out;

    // Quarter-split stft kept so the profiled slot lands on stft again.
    stft_kernel<<<1539, 128>>>(xs, xt, xg, 0);
    stft_kernel<<<1539, 128>>>(xs, xt, xg, 1539);
    stft_kernel<<<1539, 128>>>(xs, xt, xg, 3078);
    stft_kernel<<<1539, 128>>>(xs, xt, xg, 4617);
    patch_kernel<<<4290, 256>>>();
    select_kernel<<<BATCH, 256>>>();
    final_kernel<<<1, 32>>>(out);
}

// round 8
// speedup vs baseline: 2.8135x; 2.8135x over previous
#include <cuda_runtime.h>
#include <cuda_bf16.h>
#include <math.h>

// Problem constants (fixed by setup_inputs)
#define BATCH   16
#define LEN     262144
#define NFFT    1024
#define HOP     256
#define NT      1025          // frames
#define NF      513           // rfft bins (valid)
#define NFQ     528           // padded pitch (16 * 33, 16B-aligned rows)
#define NFP     33            // freq patches
#define NTP     65            // time patches
#define NP      2145          // patches per batch
#define KSEL    643           // int(2145*0.3)
#define MAGP    (BATCH*NT*NFQ)
#define NFRAMES (3*BATCH*NT)  // 49200
#define REFL2   (2*LEN - 2)   // 524286

// Scratch (static device memory; no allocation allowed)
__device__ float g_mag[3ll * MAGP];       // [sig][b][t][f(pitch 528)]
__device__ float g_kgs[BATCH * NP];
__device__ float g_pl [BATCH * NP];
__device__ float g_bsel[BATCH];
__device__ float g_bkgs[BATCH];
__device__ int   g_bpos[BATCH];

// ---- complex helpers (float2) ----
__device__ __forceinline__ float2 cadd(float2 a, float2 b) { return make_float2(a.x + b.x, a.y + b.y); }
__device__ __forceinline__ float2 csub(float2 a, float2 b) { return make_float2(a.x - b.x, a.y - b.y); }
__device__ __forceinline__ float2 cmul(float2 a, float2 b) {
    return make_float2(a.x * b.x - a.y * b.y, a.x * b.y + a.y * b.x);
}
__device__ __forceinline__ float2 cmni(float2 a) { return make_float2(a.y, -a.x); }  // * (-i)

// FFT-8, natural-order in/out, straight-line on named registers.
__device__ __forceinline__ void fft8(float2& a0, float2& a1, float2& a2, float2& a3,
                                     float2& a4, float2& a5, float2& a6, float2& a7) {
    float2 ee0 = cadd(a0, a4), ee1 = csub(a0, a4);
    float2 oo0 = cadd(a2, a6), oo1 = csub(a2, a6);
    float2 E0 = cadd(ee0, oo0), E2 = csub(ee0, oo0);
    float2 tm = cmni(oo1);
    float2 E1 = cadd(ee1, tm), E3 = csub(ee1, tm);
    float2 fe0 = cadd(a1, a5), fe1 = csub(a1, a5);
    float2 fo0 = cadd(a3, a7), fo1 = csub(a3, a7);
    float2 O0 = cadd(fe0, fo0), O2 = csub(fe0, fo0);
    float2 um = cmni(fo1);
    float2 O1 = cadd(fe1, um), O3 = csub(fe1, um);
    const float s = 0.70710678118654752f;
    float2 w1o = make_float2(s * (O1.x + O1.y), s * (O1.y - O1.x));   // w8 * O1
    float2 w3o = make_float2(s * (O3.y - O3.x), -s * (O3.x + O3.y));  // w8^3 * O3
    float2 m2  = cmni(O2);
    a0 = cadd(E0, O0);  a4 = csub(E0, O0);
    a1 = cadd(E1, w1o); a5 = csub(E1, w1o);
    a2 = cadd(E2, m2);  a6 = csub(E2, m2);
    a3 = cadd(E3, w3o); a7 = csub(E3, w3o);
}

// ---------------------------------------------------------------------------
// STFT: one frame per 64-thread group; rfft-1024 = complex FFT-512 (radix
// 8x8x8, 8 complex/thread) + real untangle. 4 frames per 256-thread block.
// ---------------------------------------------------------------------------
__global__ __launch_bounds__(256, 3) void stft2_kernel(
    const float* __restrict__ xs, const float* __restrict__ xt,
    const float* __restrict__ xg, int block0)
{
    const int tid = threadIdx.x;
    const int grp = tid >> 6;
    const int t64 = tid & 63;

    const int fid = (block0 + blockIdx.x) * 4 + grp;       // 49200 total
    int sig = fid / (BATCH * NT);
    int rem = fid - sig * (BATCH * NT);
    int b   = rem / NT;
    int t   = rem - b * NT;

    const float* x = (sig == 0) ? xs : (sig == 1 ? xt : xg);
    x += (size_t)b * LEN;
    const int F = t * HOP - 512;                           // frame start

    __shared__ float2 SH[4][2][576];
    float2* buf0 = SH[grp][0];
    float2* buf1 = SH[grp][1];

    // ---- load z[n] = x[2n] + i x[2n+1], n = t64 + 64*n2 ----
    float2 a0, a1, a2, a3, a4, a5, a6, a7;
    if (F >= 0 && F + NFFT <= LEN) {
        const float2* x2 = (const float2*)(x + F);
        a0 = x2[t64];        a1 = x2[t64 + 64];  a2 = x2[t64 + 128]; a3 = x2[t64 + 192];
        a4 = x2[t64 + 256];  a5 = x2[t64 + 320]; a6 = x2[t64 + 384]; a7 = x2[t64 + 448];
    } else {
#define LOADR(dst, K) { int g = F + 2 * (t64 + 64 * (K));                          \
        int i0 = min(abs(g), REFL2 - g); int i1 = min(abs(g + 1), REFL2 - g - 1);  \
        dst = make_float2(x[i0], x[i1]); }
        LOADR(a0, 0) LOADR(a1, 1) LOADR(a2, 2) LOADR(a3, 3)
        LOADR(a4, 4) LOADR(a5, 5) LOADR(a6, 6) LOADR(a7, 7)
#undef LOADR
    }

    const int n0 = t64 & 7;
    const int n1 = t64 >> 3;

    // ---- step A: FFT8 over n2; twiddle W64^{n1*k0} ----
    fft8(a0, a1, a2, a3, a4, a5, a6, a7);
    {
        float sn, cs;
        sincospif(-(float)n1 * (1.0f / 32.0f), &sn, &cs);
        float2 wstep = make_float2(cs, sn);
        float2 w = wstep;
        a1 = cmul(a1, w); w = cmul(w, wstep);
        a2 = cmul(a2, w); w = cmul(w, wstep);
        a3 = cmul(a3, w); w = cmul(w, wstep);
        a4 = cmul(a4, w); w = cmul(w, wstep);
        a5 = cmul(a5, w); w = cmul(w, wstep);
        a6 = cmul(a6, w); w = cmul(w, wstep);
        a7 = cmul(a7, w);
    }
    {
        const int wi = n1 * 9 + n0;
        buf0[wi]       = a0; buf0[wi + 72]  = a1; buf0[wi + 144] = a2; buf0[wi + 216] = a3;
        buf0[wi + 288] = a4; buf0[wi + 360] = a5; buf0[wi + 432] = a6; buf0[wi + 504] = a7;
    }
    __syncthreads();

    // ---- step B: gather over n1 for (n0b, k0); FFT8; twiddle W512^{n0(k0+8k1)} ----
    {
        const int n0b = t64 & 7;
        const int k0  = t64 >> 3;
        const int rb  = k0 * 72 + n0b;
        float2 b0 = buf0[rb];      float2 b1 = buf0[rb + 9];  float2 b2 = buf0[rb + 18];
        float2 b3 = buf0[rb + 27]; float2 b4 = buf0[rb + 36]; float2 b5 = buf0[rb + 45];
        float2 b6 = buf0[rb + 54]; float2 b7 = buf0[rb + 63];
        fft8(b0, b1, b2, b3, b4, b5, b6, b7);

        float sn, cs;
        sincospif(-(float)(n0b * k0) * (1.0f / 256.0f), &sn, &cs);
        float2 w = make_float2(cs, sn);                 // W512^{n0*k0}
        sincospif(-(float)n0b * (1.0f / 32.0f), &sn, &cs);
        float2 wstep = make_float2(cs, sn);             // W64^{n0}
        b0 = cmul(b0, w); w = cmul(w, wstep);
        b1 = cmul(b1, w); w = cmul(w, wstep);
        b2 = cmul(b2, w); w = cmul(w, wstep);
        b3 = cmul(b3, w); w = cmul(w, wstep);
        b4 = cmul(b4, w); w = cmul(w, wstep);
        b5 = cmul(b5, w); w = cmul(w, wstep);
        b6 = cmul(b6, w); w = cmul(w, wstep);
        b7 = cmul(b7, w);

        const int wb = k0 * 9 + n0b;
        buf1[wb]       = b0; buf1[wb + 72]  = b1; buf1[wb + 144] = b2; buf1[wb + 216] = b3;
        buf1[wb + 288] = b4; buf1[wb + 360] = b5; buf1[wb + 432] = b6; buf1[wb + 504] = b7;
    }
    __syncthreads();

    // ---- step C: gather over n0 for (k0c, k1); FFT8 -> Z; publish Z ----
    {
        const int k0c = t64 & 7;
        const int k1  = t64 >> 3;
        const int rc  = k1 * 72 + k0c * 9;
        float2 c0 = buf1[rc];     float2 c1 = buf1[rc + 1]; float2 c2 = buf1[rc + 2];
        float2 c3 = buf1[rc + 3]; float2 c4 = buf1[rc + 4]; float2 c5 = buf1[rc + 5];
        float2 c6 = buf1[rc + 6]; float2 c7 = buf1[rc + 7];
        fft8(c0, c1, c2, c3, c4, c5, c6, c7);
        // Z[t64 + 64*k2] = c_{k2}
        buf0[t64]       = c0; buf0[t64 + 64]  = c1; buf0[t64 + 128] = c2; buf0[t64 + 192] = c3;
        buf0[t64 + 256] = c4; buf0[t64 + 320] = c5; buf0[t64 + 384] = c6; buf0[t64 + 448] = c7;
    }
    __syncthreads();

    // ---- untangle rfft + magnitude; coalesced stores ----
    float* out = g_mag + (size_t)sig * MAGP + ((size_t)b * NT + t) * NFQ;
    {
        float sn, cs;
        sincospif(-(float)t64 * (1.0f / 512.0f), &sn, &cs);
        float2 w = make_float2(cs, sn);                              // e^{-i pi j/512}, j=t64
        const float2 wstep = make_float2(0.92387953251f, -0.38268343236f); // e^{-i pi/8}
#pragma unroll
        for (int c = 0; c < 8; c++) {
            int j = t64 + 64 * c;
            float2 Zj = buf0[j];
            float2 Zm = buf0[(512 - j) & 511];
            float ex = 0.5f * (Zj.x + Zm.x), ey = 0.5f * (Zj.y - Zm.y);
            float dx = 0.5f * (Zj.x - Zm.x), dy = 0.5f * (Zj.y + Zm.y);
            float ox = dy, oy = -dx;                                 // O = D * (-i)
            float xr_ = ex + (w.x * ox - w.y * oy);
            float xi_ = ey + (w.x * oy + w.y * ox);
            float mag = sqrtf(xr_ * xr_ + xi_ * xi_);
            out[j] = fmaxf(mag, 1e-8f);
            w = cmul(w, wstep);
        }
        if (t64 == 0) {
            float2 Z0 = buf0[0];
            out[512] = fmaxf(fabsf(Z0.x - Z0.y), 1e-8f);             // X[512] = ReZ0 - ImZ0
        } else if (t64 < 16) {
            out[512 + t64] = 0.f;                                    // f-padding 513..527
        }
    }
}

// ---------------------------------------------------------------------------
// Kernel 2: per-patch stats. One warp per patch; pure float4 loads on the
// 528-pitch padded layout (rows 16B-aligned). Only t-edge needs a predicate.
// ---------------------------------------------------------------------------
__global__ __launch_bounds__(256) void patch_kernel() {
    const int lane = threadIdx.x & 31;
    const int wid  = threadIdx.x >> 5;
    const int gp   = blockIdx.x * 8 + wid;         // 34320 total (exact)
    const int b  = gp / NP;
    const int p  = gp - b * NP;
    const int fp = p / NTP;
    const int tp = p - fp * NTP;

    const int dt0 = lane >> 2;       // 0..7
    const int q   = lane & 3;        // quad within 16-float row

    float sas = 0.f, sat = 0.f, ssq = 0.f;
#pragma unroll
    for (int j2 = 0; j2 < 2; j2++) {
        int t = tp * 16 + dt0 + j2 * 8;
        if (t < NT) {
            size_t idx = ((size_t)b * NT + t) * NFQ + fp * 16 + q * 4;
            float4 s4 = *(const float4*)(g_mag + idx);
            float4 t4 = *(const float4*)(g_mag + (size_t)MAGP + idx);
            float4 g4 = *(const float4*)(g_mag + 2ll * MAGP + idx);
            sas += fabsf(s4.x - g4.x) + fabsf(s4.y - g4.y)
                 + fabsf(s4.z - g4.z) + fabsf(s4.w - g4.w);
            sat += fabsf(t4.x - g4.x) + fabsf(t4.y - g4.y)
                 + fabsf(t4.z - g4.z) + fabsf(t4.w - g4.w);
            float dx = s4.x - t4.x, dy = s4.y - t4.y;
            float dz = s4.z - t4.z, dw = s4.w - t4.w;
            ssq += dx * dx + dy * dy + dz * dz + dw * dw;
        }
    }
#pragma unroll
    for (int o = 16; o; o >>= 1) {
        sas += __shfl_down_sync(0xffffffffu, sas, o);
        sat += __shfl_down_sync(0xffffffffu, sat, o);
        ssq += __shfl_down_sync(0xffffffffu, ssq, o);
    }
    if (lane == 0) {
        g_kgs[gp] = (sas - sat) * (1.0f / 256.0f);
        g_pl [gp] = ssq * (1.0f / 256.0f);
    }
}

// ---------------------------------------------------------------------------
// Kernel 3: per-batch top-k selection (exact, index-order tie-break) + stats
// ---------------------------------------------------------------------------
__device__ __forceinline__ int bredI(int v, int* scr) {
    const int tid = threadIdx.x;
#pragma unroll
    for (int o = 16; o; o >>= 1) v += __shfl_down_sync(0xffffffffu, v, o);
    __syncthreads();
    if ((tid & 31) == 0) scr[tid >> 5] = v;
    __syncthreads();
    int r = 0;
#pragma unroll
    for (int j = 0; j < 8; j++) r += scr[j];
    return r;
}
__device__ __forceinline__ float bredF(float v, float* scr) {
    const int tid = threadIdx.x;
#pragma unroll
    for (int o = 16; o; o >>= 1) v += __shfl_down_sync(0xffffffffu, v, o);
    __syncthreads();
    if ((tid & 31) == 0) scr[tid >> 5] = v;
    __syncthreads();
    float r = 0.f;
#pragma unroll
    for (int j = 0; j < 8; j++) r += scr[j];
    return r;
}

__global__ __launch_bounds__(256) void select_kernel() {
    const int b = blockIdx.x, tid = threadIdx.x;
    __shared__ unsigned su[NP];
    __shared__ float    spl[NP];
    __shared__ int      eqidx[NP];
    __shared__ int      iscr[8];
    __shared__ float    fscr[8];
    __shared__ int      eqc;

    float ksum = 0.f; int pcnt = 0;
    for (int i = tid; i < NP; i += 256) {
        float kv = g_kgs[b * NP + i];
        spl[i] = g_pl[b * NP + i];
        unsigned bits = __float_as_uint(kv);
        su[i] = (bits & 0x80000000u) ? ~bits : (bits | 0x80000000u); // order-preserving
        ksum += kv;
        pcnt += (kv > 0.f) ? 1 : 0;
    }
    if (tid == 0) eqc = 0;
    __syncthreads();

    ksum = bredF(ksum, fscr);
    pcnt = bredI(pcnt, iscr);

    // binary search for k-th largest key: max v with count(u >= v) >= KSEL
    unsigned long long lo = 0ull, hi = 0xFFFFFFFFull;
    while (lo < hi) {
        unsigned long long mid = lo + ((hi - lo + 1ull) >> 1);
        int c = 0;
        for (int i = tid; i < NP; i += 256)
            c += ((unsigned long long)su[i] >= mid) ? 1 : 0;
        c = bredI(c, iscr);
        if (c >= KSEL) lo = mid; else hi = mid - 1ull;
    }
    const unsigned v = (unsigned)lo;

    int cgt = 0; float ssel = 0.f;
    for (int i = tid; i < NP; i += 256) {
        unsigned u = su[i];
        if (u > v) { cgt++; ssel += spl[i]; }
        else if (u == v) { int pos = atomicAdd(&eqc, 1); eqidx[pos] = i; }
    }
    cgt  = bredI(cgt, iscr);
    ssel = bredF(ssel, fscr);
    __syncthreads();

    if (tid == 0) {
        int need = KSEL - cgt;         // >= 1 by construction
        int ce   = eqc;
        float extra = 0.f;
        if (need >= ce) {
            for (int j = 0; j < ce; j++) extra += spl[eqidx[j]];
        } else {
            int last = -1;
            for (int t2 = 0; t2 < need; t2++) {
                int mn = 0x7fffffff;
                for (int j = 0; j < ce; j++) {
                    int ix = eqidx[j];
                    if (ix > last && ix < mn) mn = ix;
                }
                extra += spl[mn];
                last = mn;
            }
        }
        g_bsel[b] = (ssel + extra) * (1.0f / (float)KSEL);
        g_bkgs[b] = ksum;
        g_bpos[b] = pcnt;
    }
}

// ---------------------------------------------------------------------------
// Kernel 4: finalize the 4 scalars
// ---------------------------------------------------------------------------
__global__ void final_kernel(float* __restrict__ out) {
    const int t = threadIdx.x;
    float s  = (t < BATCH) ? g_bsel[t] : 0.f;
    float kg = (t < BATCH) ? g_bkgs[t] : 0.f;
    float pc = (t < BATCH) ? (float)g_bpos[t] : 0.f;
#pragma unroll
    for (int o = 16; o; o >>= 1) {
        s  += __shfl_down_sync(0xffffffffu, s,  o);
        kg += __shfl_down_sync(0xffffffffu, kg, o);
        pc += __shfl_down_sync(0xffffffffu, pc, o);
    }
    if (t == 0) {
        out[0] = s * (1.0f / (float)BATCH);                      // loss
        out[1] = (float)KSEL / (float)NP;                        // sel_ratio
        out[2] = kg / (float)(BATCH * NP);                       // kgs_mean
        out[3] = pc / (float)(BATCH * NP);                       // kgs_pos_ratio
    }
}

extern "C" void kernel_launch(void* const* d_in, const int* in_sizes, int n_in,
                              void* d_out, int out_size) {
    const float* xs = (const float*)d_in[0];
    const float* xt = (const float*)d_in[1];
    const float* xg = (const float*)d_in[2];
    float* out = (float*)d_out;

    // 49200 frames = 12300 blocks of 4; quarter-split so the profiled slot
    // (launch position 3) lands on stft2_kernel.
    stft2_kernel<<<3075, 256>>>(xs, xt, xg, 0);
    stft2_kernel<<<3075, 256>>>(xs, xt, xg, 3075);
    stft2_kernel<<<3075, 256>>>(xs, xt, xg, 6150);
    stft2_kernel<<<3075, 256>>>(xs, xt, xg, 9225);
    patch_kernel<<<4290, 256>>>();
    select_kernel<<<BATCH, 256>>>();
    final_kernel<<<1, 32>>>(out);
}

// round 9
// speedup vs baseline: 2.8807x; 1.0239x over previous
#include <cuda_runtime.h>
#include <cuda_bf16.h>
#include <math.h>

// Problem constants (fixed by setup_inputs)
#define BATCH   16
#define LEN     262144
#define NFFT    1024
#define HOP     256
#define NT      1025          // frames
#define NF      513           // rfft bins (valid)
#define NTP     65            // time patches
#define NFP     33            // freq patches
#define NP      2145          // patches per batch (33*65)
#define KSEL    643           // int(2145*0.3)
#define REFL2   (2*LEN - 2)   // 524286

// Scratch (static device memory; no allocation allowed)
__device__ float g_kgs[BATCH * NP];
__device__ float g_pl [BATCH * NP];
__device__ float g_bsel[BATCH];
__device__ float g_bkgs[BATCH];
__device__ int   g_bpos[BATCH];

// ---- complex helpers (float2) ----
__device__ __forceinline__ float2 cadd(float2 a, float2 b) { return make_float2(a.x + b.x, a.y + b.y); }
__device__ __forceinline__ float2 csub(float2 a, float2 b) { return make_float2(a.x - b.x, a.y - b.y); }
__device__ __forceinline__ float2 cmul(float2 a, float2 b) {
    return make_float2(a.x * b.x - a.y * b.y, a.x * b.y + a.y * b.x);
}
__device__ __forceinline__ float2 cmni(float2 a) { return make_float2(a.y, -a.x); }  // * (-i)

// FFT-8, natural-order in/out, straight-line on named registers.
__device__ __forceinline__ void fft8(float2& a0, float2& a1, float2& a2, float2& a3,
                                     float2& a4, float2& a5, float2& a6, float2& a7) {
    float2 ee0 = cadd(a0, a4), ee1 = csub(a0, a4);
    float2 oo0 = cadd(a2, a6), oo1 = csub(a2, a6);
    float2 E0 = cadd(ee0, oo0), E2 = csub(ee0, oo0);
    float2 tm = cmni(oo1);
    float2 E1 = cadd(ee1, tm), E3 = csub(ee1, tm);
    float2 fe0 = cadd(a1, a5), fe1 = csub(a1, a5);
    float2 fo0 = cadd(a3, a7), fo1 = csub(a3, a7);
    float2 O0 = cadd(fe0, fo0), O2 = csub(fe0, fo0);
    float2 um = cmni(fo1);
    float2 O1 = cadd(fe1, um), O3 = csub(fe1, um);
    const float s = 0.70710678118654752f;
    float2 w1o = make_float2(s * (O1.x + O1.y), s * (O1.y - O1.x));   // w8 * O1
    float2 w3o = make_float2(s * (O3.y - O3.x), -s * (O3.x + O3.y));  // w8^3 * O3
    float2 m2  = cmni(O2);
    a0 = cadd(E0, O0);  a4 = csub(E0, O0);
    a1 = cadd(E1, w1o); a5 = csub(E1, w1o);
    a2 = cadd(E2, m2);  a6 = csub(E2, m2);
    a3 = cadd(E3, w3o); a7 = csub(E3, w3o);
}

// ---------------------------------------------------------------------------
// Fused STFT + patch kernel. Block = (batch b, time-patch tp); 192 threads =
// 3 signal-groups x 64. Each iteration computes one frame t for all three
// signals (rfft-1024 via complex FFT-512, radix 8x8x8), untangles magnitudes
// into shared, and accumulates per-f-patch |s-g|, |t-g|, (s-t)^2 in registers.
// Twiddles come from per-block shared tables (built once, reused 48x).
// ---------------------------------------------------------------------------
__global__ __launch_bounds__(192, 5) void fused_kernel(
    const float* __restrict__ xs, const float* __restrict__ xt,
    const float* __restrict__ xg)
{
    const int tid = threadIdx.x;
    const int grp = tid / 64;          // which signal
    const int t64 = tid & 63;
    const int b   = blockIdx.x / NTP;
    const int tp  = blockIdx.x - b * NTP;

    __shared__ float2 SH[3][2][576];   // per-signal ping-pong FFT slabs
    __shared__ float2 tw_a[64];        // W64^{n1*c}
    __shared__ float2 tw_b[512];       // [c*64+t64] = W512^{n0*(k0+8c)}
    __shared__ float2 tw_u[512];       // e^{-i pi j/512}
    __shared__ float  pacc[NFP][4];    // per-f-patch sums: S, T, P

    // ---- build twiddle tables + zero accumulators (once per block) ----
    for (int idx = tid; idx < 1088; idx += 192) {
        float sn, cs;
        if (idx < 64) {
            int n1 = idx >> 3, c = idx & 7;
            sincospif(-(float)(n1 * c) * (1.0f / 32.0f), &sn, &cs);
            tw_a[idx] = make_float2(cs, sn);
        } else if (idx < 576) {
            int e = idx - 64; int c = e >> 6; int t_ = e & 63;
            int n0b = t_ & 7, k0 = t_ >> 3;
            sincospif(-(float)(n0b * (k0 + 8 * c)) * (1.0f / 256.0f), &sn, &cs);
            tw_b[e] = make_float2(cs, sn);
        } else {
            int j = idx - 576;
            sincospif(-(float)j * (1.0f / 512.0f), &sn, &cs);
            tw_u[j] = make_float2(cs, sn);
        }
    }
    if (tid < NFP) { pacc[tid][0] = 0.f; pacc[tid][1] = 0.f; pacc[tid][2] = 0.f; }
    __syncthreads();

    const float* x = (grp == 0 ? xs : (grp == 1 ? xt : xg)) + (size_t)b * LEN;
    float2* buf0 = SH[grp][0];
    float2* buf1 = SH[grp][1];

    const int n1A = t64 >> 3;          // step-A row
    const int n0A = t64 & 7;

    // per-thread patch accumulators (f = tid, tid+192, tid+384)
    float aS0 = 0.f, aT0 = 0.f, aP0 = 0.f;
    float aS1 = 0.f, aT1 = 0.f, aP1 = 0.f;
    float aS2 = 0.f, aT2 = 0.f, aP2 = 0.f;

    for (int it = 0; it < 16; it++) {
        const int t = tp * 16 + it;
        if (t >= NT) break;                          // uniform across block
        const int F = t * HOP - 512;

        // ---- load z[n] = x[2n] + i x[2n+1], n = t64 + 64*k ----
        float2 a0, a1, a2, a3, a4, a5, a6, a7;
        if (F >= 0 && F + NFFT <= LEN) {
            const float2* x2 = (const float2*)(x + F);
            a0 = x2[t64];       a1 = x2[t64 + 64];  a2 = x2[t64 + 128]; a3 = x2[t64 + 192];
            a4 = x2[t64 + 256]; a5 = x2[t64 + 320]; a6 = x2[t64 + 384]; a7 = x2[t64 + 448];
        } else {
#define LOADR(dst, K) { int g = F + 2 * (t64 + 64 * (K));                          \
            int i0 = min(abs(g), REFL2 - g); int i1 = min(abs(g + 1), REFL2 - g - 1); \
            dst = make_float2(x[i0], x[i1]); }
            LOADR(a0, 0) LOADR(a1, 1) LOADR(a2, 2) LOADR(a3, 3)
            LOADR(a4, 4) LOADR(a5, 5) LOADR(a6, 6) LOADR(a7, 7)
#undef LOADR
        }

        // ---- step A: FFT8 over n2; twiddle from table ----
        fft8(a0, a1, a2, a3, a4, a5, a6, a7);
        a1 = cmul(a1, tw_a[n1A * 8 + 1]);
        a2 = cmul(a2, tw_a[n1A * 8 + 2]);
        a3 = cmul(a3, tw_a[n1A * 8 + 3]);
        a4 = cmul(a4, tw_a[n1A * 8 + 4]);
        a5 = cmul(a5, tw_a[n1A * 8 + 5]);
        a6 = cmul(a6, tw_a[n1A * 8 + 6]);
        a7 = cmul(a7, tw_a[n1A * 8 + 7]);
        {
            const int wi = n1A * 9 + n0A;
            buf0[wi]       = a0; buf0[wi + 72]  = a1; buf0[wi + 144] = a2; buf0[wi + 216] = a3;
            buf0[wi + 288] = a4; buf0[wi + 360] = a5; buf0[wi + 432] = a6; buf0[wi + 504] = a7;
        }
        __syncthreads();

        // ---- step B: gather over n1; FFT8; twiddle from table ----
        {
            const int n0b = t64 & 7;
            const int k0  = t64 >> 3;
            const int rb  = k0 * 72 + n0b;
            float2 b0 = buf0[rb];      float2 b1 = buf0[rb + 9];  float2 b2 = buf0[rb + 18];
            float2 b3 = buf0[rb + 27]; float2 b4 = buf0[rb + 36]; float2 b5 = buf0[rb + 45];
            float2 b6 = buf0[rb + 54]; float2 b7 = buf0[rb + 63];
            fft8(b0, b1, b2, b3, b4, b5, b6, b7);
            b0 = cmul(b0, tw_b[t64]);
            b1 = cmul(b1, tw_b[64  + t64]);
            b2 = cmul(b2, tw_b[128 + t64]);
            b3 = cmul(b3, tw_b[192 + t64]);
            b4 = cmul(b4, tw_b[256 + t64]);
            b5 = cmul(b5, tw_b[320 + t64]);
            b6 = cmul(b6, tw_b[384 + t64]);
            b7 = cmul(b7, tw_b[448 + t64]);
            const int wb = k0 * 9 + n0b;
            buf1[wb]       = b0; buf1[wb + 72]  = b1; buf1[wb + 144] = b2; buf1[wb + 216] = b3;
            buf1[wb + 288] = b4; buf1[wb + 360] = b5; buf1[wb + 432] = b6; buf1[wb + 504] = b7;
        }
        __syncthreads();

        // ---- step C: gather over n0; FFT8 -> Z; publish to buf0 ----
        {
            const int k0c = t64 & 7;
            const int k1  = t64 >> 3;
            const int rc  = k1 * 72 + k0c * 9;
            float2 c0 = buf1[rc];     float2 c1 = buf1[rc + 1]; float2 c2 = buf1[rc + 2];
            float2 c3 = buf1[rc + 3]; float2 c4 = buf1[rc + 4]; float2 c5 = buf1[rc + 5];
            float2 c6 = buf1[rc + 6]; float2 c7 = buf1[rc + 7];
            fft8(c0, c1, c2, c3, c4, c5, c6, c7);
            buf0[t64]       = c0; buf0[t64 + 64]  = c1; buf0[t64 + 128] = c2; buf0[t64 + 192] = c3;
            buf0[t64 + 256] = c4; buf0[t64 + 320] = c5; buf0[t64 + 384] = c6; buf0[t64 + 448] = c7;
        }
        __syncthreads();

        // ---- untangle rfft + magnitude into shared (reuse buf1 as float*) ----
        {
            float* mg = (float*)buf1;
#pragma unroll
            for (int c = 0; c < 8; c++) {
                int j = t64 + 64 * c;
                float2 Zj = buf0[j];
                float2 Zm = buf0[(512 - j) & 511];
                float2 w  = tw_u[j];
                float ex = 0.5f * (Zj.x + Zm.x), ey = 0.5f * (Zj.y - Zm.y);
                float dx = 0.5f * (Zj.x - Zm.x), dy = 0.5f * (Zj.y + Zm.y);
                float ox = dy, oy = -dx;
                float xr_ = ex + (w.x * ox - w.y * oy);
                float xi_ = ey + (w.x * oy + w.y * ox);
                mg[j] = fmaxf(sqrtf(xr_ * xr_ + xi_ * xi_), 1e-8f);
            }
            if (t64 == 0) {
                float2 Z0 = buf0[0];
                mg[512] = fmaxf(fabsf(Z0.x - Z0.y), 1e-8f);
            }
        }
        __syncthreads();

        // ---- accumulate patch partial sums (all 192 threads) ----
        {
            const float* ms = (const float*)SH[0][1];
            const float* mt = (const float*)SH[1][1];
            const float* mgd = (const float*)SH[2][1];
            {
                int f = tid;                       // 0..191
                float s = ms[f], tt = mt[f], g = mgd[f];
                aS0 += fabsf(s - g); aT0 += fabsf(tt - g);
                float d = s - tt; aP0 += d * d;
            }
            {
                int f = tid + 192;                 // 192..383
                float s = ms[f], tt = mt[f], g = mgd[f];
                aS1 += fabsf(s - g); aT1 += fabsf(tt - g);
                float d = s - tt; aP1 += d * d;
            }
            if (tid + 384 < NF) {                  // 384..512
                int f = tid + 384;
                float s = ms[f], tt = mt[f], g = mgd[f];
                aS2 += fabsf(s - g); aT2 += fabsf(tt - g);
                float d = s - tt; aP2 += d * d;
            }
        }
        __syncthreads();   // protect bufs before next iteration
    }

    // ---- fold per-thread accumulators into per-f-patch sums ----
    {
        int f0 = tid;
        atomicAdd(&pacc[f0 >> 4][0], aS0);
        atomicAdd(&pacc[f0 >> 4][1], aT0);
        atomicAdd(&pacc[f0 >> 4][2], aP0);
        int f1 = tid + 192;
        atomicAdd(&pacc[f1 >> 4][0], aS1);
        atomicAdd(&pacc[f1 >> 4][1], aT1);
        atomicAdd(&pacc[f1 >> 4][2], aP1);
        if (tid + 384 < NF) {
            int f2 = tid + 384;
            atomicAdd(&pacc[f2 >> 4][0], aS2);
            atomicAdd(&pacc[f2 >> 4][1], aT2);
            atomicAdd(&pacc[f2 >> 4][2], aP2);
        }
    }
    __syncthreads();

    if (tid < NFP) {
        int p = b * NP + tid * NTP + tp;           // patch index (fp-major)
        g_kgs[p] = (pacc[tid][0] - pacc[tid][1]) * (1.0f / 256.0f);
        g_pl [p] = pacc[tid][2] * (1.0f / 256.0f);
    }
}

// ---------------------------------------------------------------------------
// Kernel 3: per-batch top-k selection (exact, index-order tie-break) + stats
// ---------------------------------------------------------------------------
__device__ __forceinline__ int bredI(int v, int* scr) {
    const int tid = threadIdx.x;
#pragma unroll
    for (int o = 16; o; o >>= 1) v += __shfl_down_sync(0xffffffffu, v, o);
    __syncthreads();
    if ((tid & 31) == 0) scr[tid >> 5] = v;
    __syncthreads();
    int r = 0;
#pragma unroll
    for (int j = 0; j < 8; j++) r += scr[j];
    return r;
}
__device__ __forceinline__ float bredF(float v, float* scr) {
    const int tid = threadIdx.x;
#pragma unroll
    for (int o = 16; o; o >>= 1) v += __shfl_down_sync(0xffffffffu, v, o);
    __syncthreads();
    if ((tid & 31) == 0) scr[tid >> 5] = v;
    __syncthreads();
    float r = 0.f;
#pragma unroll
    for (int j = 0; j < 8; j++) r += scr[j];
    return r;
}

__global__ __launch_bounds__(256) void select_kernel() {
    const int b = blockIdx.x, tid = threadIdx.x;
    __shared__ unsigned su[NP];
    __shared__ float    spl[NP];
    __shared__ int      eqidx[NP];
    __shared__ int      iscr[8];
    __shared__ float    fscr[8];
    __shared__ int      eqc;

    float ksum = 0.f; int pcnt = 0;
    for (int i = tid; i < NP; i += 256) {
        float kv = g_kgs[b * NP + i];
        spl[i] = g_pl[b * NP + i];
        unsigned bits = __float_as_uint(kv);
        su[i] = (bits & 0x80000000u) ? ~bits : (bits | 0x80000000u); // order-preserving
        ksum += kv;
        pcnt += (kv > 0.f) ? 1 : 0;
    }
    if (tid == 0) eqc = 0;
    __syncthreads();

    ksum = bredF(ksum, fscr);
    pcnt = bredI(pcnt, iscr);

    // binary search for k-th largest key: max v with count(u >= v) >= KSEL
    unsigned long long lo = 0ull, hi = 0xFFFFFFFFull;
    while (lo < hi) {
        unsigned long long mid = lo + ((hi - lo + 1ull) >> 1);
        int c = 0;
        for (int i = tid; i < NP; i += 256)
            c += ((unsigned long long)su[i] >= mid) ? 1 : 0;
        c = bredI(c, iscr);
        if (c >= KSEL) lo = mid; else hi = mid - 1ull;
    }
    const unsigned v = (unsigned)lo;

    int cgt = 0; float ssel = 0.f;
    for (int i = tid; i < NP; i += 256) {
        unsigned u = su[i];
        if (u > v) { cgt++; ssel += spl[i]; }
        else if (u == v) { int pos = atomicAdd(&eqc, 1); eqidx[pos] = i; }
    }
    cgt  = bredI(cgt, iscr);
    ssel = bredF(ssel, fscr);
    __syncthreads();

    if (tid == 0) {
        int need = KSEL - cgt;         // >= 1 by construction
        int ce   = eqc;
        float extra = 0.f;
        if (need >= ce) {
            for (int j = 0; j < ce; j++) extra += spl[eqidx[j]];
        } else {
            int last = -1;
            for (int t2 = 0; t2 < need; t2++) {
                int mn = 0x7fffffff;
                for (int j = 0; j < ce; j++) {
                    int ix = eqidx[j];
                    if (ix > last && ix < mn) mn = ix;
                }
                extra += spl[mn];
                last = mn;
            }
        }
        g_bsel[b] = (ssel + extra) * (1.0f / (float)KSEL);
        g_bkgs[b] = ksum;
        g_bpos[b] = pcnt;
    }
}

// ---------------------------------------------------------------------------
// Kernel 4: finalize the 4 scalars
// ---------------------------------------------------------------------------
__global__ void final_kernel(float* __restrict__ out) {
    const int t = threadIdx.x;
    float s  = (t < BATCH) ? g_bsel[t] : 0.f;
    float kg = (t < BATCH) ? g_bkgs[t] : 0.f;
    float pc = (t < BATCH) ? (float)g_bpos[t] : 0.f;
#pragma unroll
    for (int o = 16; o; o >>= 1) {
        s  += __shfl_down_sync(0xffffffffu, s,  o);
        kg += __shfl_down_sync(0xffffffffu, kg, o);
        pc += __shfl_down_sync(0xffffffffu, pc, o);
    }
    if (t == 0) {
        out[0] = s * (1.0f / (float)BATCH);                      // loss
        out[1] = (float)KSEL / (float)NP;                        // sel_ratio
        out[2] = kg / (float)(BATCH * NP);                       // kgs_mean
        out[3] = pc / (float)(BATCH * NP);                       // kgs_pos_ratio
    }
}

extern "C" void kernel_launch(void* const* d_in, const int* in_sizes, int n_in,
                              void* d_out, int out_size) {
    const float* xs = (const float*)d_in[0];
    const float* xt = (const float*)d_in[1];
    const float* xg = (const float*)d_in[2];
    float* out = (float*)d_out;

    fused_kernel<<<BATCH * NTP, 192>>>(xs, xt, xg);   // 1040 blocks
    select_kernel<<<BATCH, 256>>>();
    final_kernel<<<1, 32>>>(out);
}